// round 2
// baseline (speedup 1.0000x reference)
#include <cuda_runtime.h>
#include <cuda_bf16.h>

// Problem constants
#define BATCH 4
#define SEQ   4096
#define DIM   1024

// GEMM tile config
#define BM 128
#define BN 128
#define BK 16
#define NSTAGE 3
#define ASTAGE (BM * BK)   // floats per A stage (2048)
#define BSTAGE (BN * BK)

// Scratch (allocation-free rule: __device__ globals)
__device__ float g_X [(long long)BATCH*SEQ*DIM];   // tf32-rounded x
__device__ float g_Wq[(long long)DIM*DIM];
__device__ float g_Wk[(long long)DIM*DIM];
__device__ float g_Wv[(long long)DIM*DIM];
__device__ float g_Q [(long long)BATCH*SEQ*DIM];
__device__ float g_K [(long long)BATCH*SEQ*DIM];
__device__ float g_Vt[(long long)BATCH*SEQ*DIM];   // layout [e][b*SEQ + t] (ld = BATCH*SEQ)
__device__ float g_S [(long long)BATCH*SEQ*SEQ];   // scores / probs, 256 MB

__device__ __forceinline__ float f2tf(float f) {
    unsigned u;
    asm("cvt.rna.tf32.f32 %0, %1;" : "=r"(u) : "f"(f));
    return __uint_as_float(u);
}

__device__ __forceinline__ void cp4(void* sm, const void* gm) {
    unsigned s = (unsigned)__cvta_generic_to_shared(sm);
    asm volatile("cp.async.ca.shared.global [%0], [%1], 4;" :: "r"(s), "l"(gm));
}

// Elementwise tf32 rounding (float4 granularity; n % 4 == 0 for all our tensors)
__global__ void round_tf32_kernel(const float* __restrict__ in, float* __restrict__ out,
                                  long long n) {
    long long i = ((long long)blockIdx.x * blockDim.x + threadIdx.x) * 4;
    if (i < n) {
        float4 v = *(const float4*)(in + i);
        v.x = f2tf(v.x); v.y = f2tf(v.y); v.z = f2tf(v.z); v.w = f2tf(v.w);
        *(float4*)(out + i) = v;
    }
}

// C[M,N] = alpha * A[M,K] * B[N,K]^T   (both operands K-contiguous, tf32-pre-rounded)
// SMEM k-permuted layout: row-chunk p (float index) holds k = (p%4)*4 + p/4, so one
// LDS.128 at chunk tg yields k = {tg, tg+4, tg+8, tg+12} = fragments for both k8 steps.
// TRANS: store C transposed as C[n*ldc + m]. ROUND: tf32-round outputs.
template<bool TRANS, bool ROUND>
__global__ void __launch_bounds__(256, 2) gemm_tf32(
    const float* __restrict__ A, const float* __restrict__ B, float* __restrict__ C,
    int lda, int ldb, int ldc,
    long long sA, long long sB, long long sC,
    int K, float alpha)
{
    __shared__ float As[NSTAGE * ASTAGE];
    __shared__ float Bs[NSTAGE * BSTAGE];

    const float* Ab = A + (long long)blockIdx.z * sA + (long long)blockIdx.y * BM * lda;
    const float* Bb = B + (long long)blockIdx.z * sB + (long long)blockIdx.x * BN * ldb;
    float*       Cb = C + (long long)blockIdx.z * sC;

    const int tid  = threadIdx.x;
    const int lane = tid & 31;
    const int warp = tid >> 5;
    const int wm = warp >> 2;      // 0..1
    const int wn = warp & 3;       // 0..3
    const int g  = lane >> 2;      // group id 0..7
    const int tg = lane & 3;       // thread-in-group 0..3

    // Loader thread mapping: 16 rows per pass (row = tid>>4 + i*16), k = tid&15
    const int ldr = tid >> 4;
    const int ldk = tid & 15;
    const int sig = (ldk & 3) * 4 + (ldk >> 2);   // permuted position of k
    const float* Agl = Ab + (long long)ldr * lda + ldk;
    const float* Bgl = Bb + (long long)ldr * ldb + ldk;

    float acc[4][4][4];
    #pragma unroll
    for (int i = 0; i < 4; i++)
        #pragma unroll
        for (int j = 0; j < 4; j++)
            #pragma unroll
            for (int c = 0; c < 4; c++) acc[i][j][c] = 0.f;

    const int KT = K / BK;

    auto load = [&](int kt, int st) {
        if (kt < KT) {
            float* sa = As + st * ASTAGE;
            float* sb = Bs + st * BSTAGE;
            const float* ga = Agl + kt * BK;
            const float* gb = Bgl + kt * BK;
            #pragma unroll
            for (int i = 0; i < 8; i++)
                cp4(&sa[(ldr + i * 16) * BK + sig], ga + (long long)(i * 16) * lda);
            #pragma unroll
            for (int i = 0; i < 8; i++)
                cp4(&sb[(ldr + i * 16) * BK + sig], gb + (long long)(i * 16) * ldb);
        }
        asm volatile("cp.async.commit_group;");
    };

    load(0, 0);
    load(1, 1);

    for (int kt = 0; kt < KT; kt++) {
        load(kt + 2, (kt + 2) % NSTAGE);
        asm volatile("cp.async.wait_group 2;");
        __syncthreads();

        const float* as = As + (kt % NSTAGE) * ASTAGE;
        const float* bs = Bs + (kt % NSTAGE) * BSTAGE;

        // B fragments: one LDS.128 per nt covers both k8 steps
        float4 bb[4];
        #pragma unroll
        for (int nt = 0; nt < 4; nt++) {
            int c0 = wn * 32 + nt * 8;
            bb[nt] = *(const float4*)&bs[(c0 + g) * BK + tg * 4];
        }

        #pragma unroll
        for (int mt = 0; mt < 4; mt++) {
            int r0 = wm * 64 + mt * 16;
            float4 alo = *(const float4*)&as[(r0 + g    ) * BK + tg * 4];
            float4 ahi = *(const float4*)&as[(r0 + g + 8) * BK + tg * 4];
            // ks = 0: A frag = {alo.x, ahi.x, alo.y, ahi.y}, B frag = {bb.x, bb.y}
            #pragma unroll
            for (int nt = 0; nt < 4; nt++)
                asm volatile(
                    "mma.sync.aligned.m16n8k8.row.col.f32.tf32.tf32.f32 "
                    "{%0,%1,%2,%3}, {%4,%5,%6,%7}, {%8,%9}, {%0,%1,%2,%3};"
                    : "+f"(acc[mt][nt][0]), "+f"(acc[mt][nt][1]),
                      "+f"(acc[mt][nt][2]), "+f"(acc[mt][nt][3])
                    : "r"(__float_as_uint(alo.x)), "r"(__float_as_uint(ahi.x)),
                      "r"(__float_as_uint(alo.y)), "r"(__float_as_uint(ahi.y)),
                      "r"(__float_as_uint(bb[nt].x)), "r"(__float_as_uint(bb[nt].y)));
            // ks = 8: A frag = {alo.z, ahi.z, alo.w, ahi.w}, B frag = {bb.z, bb.w}
            #pragma unroll
            for (int nt = 0; nt < 4; nt++)
                asm volatile(
                    "mma.sync.aligned.m16n8k8.row.col.f32.tf32.tf32.f32 "
                    "{%0,%1,%2,%3}, {%4,%5,%6,%7}, {%8,%9}, {%0,%1,%2,%3};"
                    : "+f"(acc[mt][nt][0]), "+f"(acc[mt][nt][1]),
                      "+f"(acc[mt][nt][2]), "+f"(acc[mt][nt][3])
                    : "r"(__float_as_uint(alo.z)), "r"(__float_as_uint(ahi.z)),
                      "r"(__float_as_uint(alo.w)), "r"(__float_as_uint(ahi.w)),
                      "r"(__float_as_uint(bb[nt].z)), "r"(__float_as_uint(bb[nt].w)));
        }
        __syncthreads();
    }

    // Epilogue
    #pragma unroll
    for (int mt = 0; mt < 4; mt++) {
        int row0 = blockIdx.y * BM + wm * 64 + mt * 16 + g;
        #pragma unroll
        for (int nt = 0; nt < 4; nt++) {
            int col0 = blockIdx.x * BN + wn * 32 + nt * 8 + 2 * tg;
            float v0 = acc[mt][nt][0] * alpha;
            float v1 = acc[mt][nt][1] * alpha;
            float v2 = acc[mt][nt][2] * alpha;
            float v3 = acc[mt][nt][3] * alpha;
            if (ROUND) { v0 = f2tf(v0); v1 = f2tf(v1); v2 = f2tf(v2); v3 = f2tf(v3); }
            if (!TRANS) {
                *(float2*)&Cb[(long long)(row0    ) * ldc + col0] = make_float2(v0, v1);
                *(float2*)&Cb[(long long)(row0 + 8) * ldc + col0] = make_float2(v2, v3);
            } else {
                Cb[(long long)(col0    ) * ldc + row0    ] = v0;
                Cb[(long long)(col0 + 1) * ldc + row0    ] = v1;
                Cb[(long long)(col0    ) * ldc + row0 + 8] = v2;
                Cb[(long long)(col0 + 1) * ldc + row0 + 8] = v3;
            }
        }
    }
}

// Row softmax over SEQ-length rows, one block per row, in place; tf32-rounds output.
__global__ void softmax_kernel(float* __restrict__ S) {
    long long row = blockIdx.x;
    float4* p4 = (float4*)(S + row * SEQ);
    const int tid = threadIdx.x, lane = tid & 31, warp = tid >> 5;
    __shared__ float rmax[8], rsum[8];

    float4 v[4];
    float mx = -1e30f;
    #pragma unroll
    for (int i = 0; i < 4; i++) {
        v[i] = p4[tid + i * 256];
        mx = fmaxf(mx, fmaxf(fmaxf(v[i].x, v[i].y), fmaxf(v[i].z, v[i].w)));
    }
    #pragma unroll
    for (int o = 16; o > 0; o >>= 1) mx = fmaxf(mx, __shfl_xor_sync(0xffffffffu, mx, o));
    if (lane == 0) rmax[warp] = mx;
    __syncthreads();
    float gm = rmax[0];
    #pragma unroll
    for (int j = 1; j < 8; j++) gm = fmaxf(gm, rmax[j]);

    float s = 0.f;
    #pragma unroll
    for (int i = 0; i < 4; i++) {
        v[i].x = __expf(v[i].x - gm);
        v[i].y = __expf(v[i].y - gm);
        v[i].z = __expf(v[i].z - gm);
        v[i].w = __expf(v[i].w - gm);
        s += v[i].x + v[i].y + v[i].z + v[i].w;
    }
    #pragma unroll
    for (int o = 16; o > 0; o >>= 1) s += __shfl_xor_sync(0xffffffffu, s, o);
    if (lane == 0) rsum[warp] = s;
    __syncthreads();
    float gs = 0.f;
    #pragma unroll
    for (int j = 0; j < 8; j++) gs += rsum[j];
    float inv = 1.f / gs;

    #pragma unroll
    for (int i = 0; i < 4; i++) {
        v[i].x = f2tf(v[i].x * inv);
        v[i].y = f2tf(v[i].y * inv);
        v[i].z = f2tf(v[i].z * inv);
        v[i].w = f2tf(v[i].w * inv);
        p4[tid + i * 256] = v[i];
    }
}

extern "C" void kernel_launch(void* const* d_in, const int* in_sizes, int n_in,
                              void* d_out, int out_size) {
    const float* x  = (const float*)d_in[0];
    const float* Wq = (const float*)d_in[1];
    const float* Wk = (const float*)d_in[2];
    const float* Wv = (const float*)d_in[3];
    float* out = (float*)d_out;

    float *pX, *pWq, *pWk, *pWv, *pQ, *pK, *pVt, *pS;
    cudaGetSymbolAddress((void**)&pX,  g_X);
    cudaGetSymbolAddress((void**)&pWq, g_Wq);
    cudaGetSymbolAddress((void**)&pWk, g_Wk);
    cudaGetSymbolAddress((void**)&pWv, g_Wv);
    cudaGetSymbolAddress((void**)&pQ,  g_Q);
    cudaGetSymbolAddress((void**)&pK,  g_K);
    cudaGetSymbolAddress((void**)&pVt, g_Vt);
    cudaGetSymbolAddress((void**)&pS,  g_S);

    const long long BT = (long long)BATCH * SEQ;            // 16384
    const long long nX = BT * DIM;                          // 16M
    const long long nW = (long long)DIM * DIM;              // 1M
    const long long strideQK = (long long)SEQ * DIM;
    const long long strideS  = (long long)SEQ * SEQ;

    // Pre-round all GEMM inputs to tf32 (removes all in-loop cvt)
    round_tf32_kernel<<<(unsigned)(nX / 4 / 256), 256>>>(x,  pX,  nX);
    round_tf32_kernel<<<(unsigned)(nW / 4 / 256), 256>>>(Wq, pWq, nW);
    round_tf32_kernel<<<(unsigned)(nW / 4 / 256), 256>>>(Wk, pWk, nW);
    round_tf32_kernel<<<(unsigned)(nW / 4 / 256), 256>>>(Wv, pWv, nW);

    // Projections over flattened [B*T, D]; outputs tf32-rounded in epilogue
    dim3 gProj(DIM / BN, (unsigned)(BT / BM), 1);
    gemm_tf32<false, true><<<gProj, 256>>>(pX, pWq, pQ,  DIM, DIM, DIM,     0, 0, 0, DIM, 1.0f);
    gemm_tf32<false, true><<<gProj, 256>>>(pX, pWk, pK,  DIM, DIM, DIM,     0, 0, 0, DIM, 1.0f);
    gemm_tf32<true , true><<<gProj, 256>>>(pX, pWv, pVt, DIM, DIM, (int)BT, 0, 0, 0, DIM, 1.0f);

    // Scores: S_b = (Q_b K_b^T) / sqrt(D)   (softmax rounds its own output)
    dim3 gS(SEQ / BN, SEQ / BM, BATCH);
    gemm_tf32<false, false><<<gS, 256>>>(pQ, pK, pS, DIM, DIM, SEQ,
                                         strideQK, strideQK, strideS, DIM, 0.03125f);

    // Row softmax, in place (tf32-rounds probs)
    softmax_kernel<<<(unsigned)BT, 256>>>(pS);

    // Output: O_b = P_b V_b   (V^T layout: element (e, t) at e*BT + b*SEQ + t)
    dim3 gO(DIM / BN, SEQ / BM, BATCH);
    gemm_tf32<false, false><<<gO, 256>>>(pS, pVt, out, SEQ, (int)BT, DIM,
                                         strideS, (long long)SEQ, (long long)SEQ * DIM,
                                         SEQ, 1.0f);
}

// round 3
// speedup vs baseline: 1.2145x; 1.2145x over previous
#include <cuda_runtime.h>
#include <cuda_bf16.h>

// Problem constants
#define BATCH 4
#define SEQ   4096
#define DIM   1024

// GEMM tile config
#define BM 128
#define BN 128
#define BK 16
#define NSTAGE 3
#define ASTAGE (BM * BK)   // floats per A stage (2048)
#define BSTAGE (BN * BK)

// Scratch (allocation-free rule: __device__ globals)
__device__ float g_X [(long long)BATCH*SEQ*DIM];   // tf32-rounded x
__device__ float g_Wq[(long long)DIM*DIM];
__device__ float g_Wk[(long long)DIM*DIM];
__device__ float g_Wv[(long long)DIM*DIM];
__device__ float g_Q [(long long)BATCH*SEQ*DIM];
__device__ float g_K [(long long)BATCH*SEQ*DIM];
__device__ float g_Vt[(long long)BATCH*SEQ*DIM];   // layout [e][b*SEQ + t] (ld = BATCH*SEQ)
__device__ float g_S [(long long)BATCH*SEQ*SEQ];   // scores / probs, 256 MB

__device__ __forceinline__ float f2tf(float f) {
    unsigned u;
    asm("cvt.rna.tf32.f32 %0, %1;" : "=r"(u) : "f"(f));
    return __uint_as_float(u);
}

__device__ __forceinline__ void cp16(void* sm, const void* gm) {
    unsigned s = (unsigned)__cvta_generic_to_shared(sm);
    asm volatile("cp.async.cg.shared.global [%0], [%1], 16;" :: "r"(s), "l"(gm));
}

// Elementwise tf32 rounding (float4 granularity; n % 4 == 0 for all our tensors)
__global__ void round_tf32_kernel(const float* __restrict__ in, float* __restrict__ out,
                                  long long n) {
    long long i = ((long long)blockIdx.x * blockDim.x + threadIdx.x) * 4;
    if (i < n) {
        float4 v = *(const float4*)(in + i);
        v.x = f2tf(v.x); v.y = f2tf(v.y); v.z = f2tf(v.z); v.w = f2tf(v.w);
        *(float4*)(out + i) = v;
    }
}

// C[M,N] = alpha * A[M,K] * B[N,K]^T  (both operands K-contiguous, tf32-pre-rounded)
//
// SMEM natural row layout (row stride BK floats). Fragment trick: one LDS.128 per
// row gives thread tg the k-values {4tg..4tg+3}. MMA step A uses (k 4tg, 4tg+1) for
// both A and B fragments, step B uses (4tg+2, 4tg+3). The quad's k-cover is a
// permutation of 0..15 consistent between A and B, so the dot product is exact.
//
// TRANS: store C transposed as C[n*ldc + m]. ROUND: tf32-round outputs.
template<bool TRANS, bool ROUND>
__global__ void __launch_bounds__(256, 2) gemm_tf32(
    const float* __restrict__ A, const float* __restrict__ B, float* __restrict__ C,
    int lda, int ldb, int ldc,
    long long sA, long long sB, long long sC,
    int K, float alpha)
{
    __shared__ float As[NSTAGE * ASTAGE];
    __shared__ float Bs[NSTAGE * BSTAGE];

    const float* Ab = A + (long long)blockIdx.z * sA + (long long)blockIdx.y * BM * lda;
    const float* Bb = B + (long long)blockIdx.z * sB + (long long)blockIdx.x * BN * ldb;
    float*       Cb = C + (long long)blockIdx.z * sC;

    const int tid  = threadIdx.x;
    const int lane = tid & 31;
    const int warp = tid >> 5;
    const int wm = warp >> 2;      // 0..1
    const int wn = warp & 3;       // 0..3
    const int g  = lane >> 2;      // group id 0..7
    const int tg = lane & 3;       // thread-in-group 0..3

    // Loader: thread handles chunk ch = tid + i*256; row = ch>>2, 16B chunk kc = ch&3
    const int ldr = tid >> 2;
    const int ldc4 = (tid & 3) * 4;
    const float* Agl = Ab + (long long)ldr * lda + ldc4;
    const float* Bgl = Bb + (long long)ldr * ldb + ldc4;

    float acc[4][4][4];
    #pragma unroll
    for (int i = 0; i < 4; i++)
        #pragma unroll
        for (int j = 0; j < 4; j++)
            #pragma unroll
            for (int c = 0; c < 4; c++) acc[i][j][c] = 0.f;

    const int KT = K / BK;

    auto load = [&](int kt, int st) {
        if (kt < KT) {
            float* sa = As + st * ASTAGE;
            float* sb = Bs + st * BSTAGE;
            #pragma unroll
            for (int i = 0; i < 2; i++)
                cp16(&sa[(ldr + i * 64) * BK + ldc4],
                     Agl + kt * BK + (long long)(i * 64) * lda);
            #pragma unroll
            for (int i = 0; i < 2; i++)
                cp16(&sb[(ldr + i * 64) * BK + ldc4],
                     Bgl + kt * BK + (long long)(i * 64) * ldb);
        }
        asm volatile("cp.async.commit_group;");
    };

    load(0, 0);
    load(1, 1);

    for (int kt = 0; kt < KT; kt++) {
        load(kt + 2, (kt + 2) % NSTAGE);
        asm volatile("cp.async.wait_group 2;");
        __syncthreads();

        const float* as = As + (kt % NSTAGE) * ASTAGE;
        const float* bs = Bs + (kt % NSTAGE) * BSTAGE;

        // B fragments: one LDS.128 per nt covers both MMA steps
        float4 bb[4];
        #pragma unroll
        for (int nt = 0; nt < 4; nt++) {
            int c0 = wn * 32 + nt * 8;
            bb[nt] = *(const float4*)&bs[(c0 + g) * BK + tg * 4];
        }

        #pragma unroll
        for (int mt = 0; mt < 4; mt++) {
            int r0 = wm * 64 + mt * 16;
            float4 alo = *(const float4*)&as[(r0 + g    ) * BK + tg * 4];
            float4 ahi = *(const float4*)&as[(r0 + g + 8) * BK + tg * 4];
            // step A: thread k = {4tg, 4tg+1}
            #pragma unroll
            for (int nt = 0; nt < 4; nt++)
                asm volatile(
                    "mma.sync.aligned.m16n8k8.row.col.f32.tf32.tf32.f32 "
                    "{%0,%1,%2,%3}, {%4,%5,%6,%7}, {%8,%9}, {%0,%1,%2,%3};"
                    : "+f"(acc[mt][nt][0]), "+f"(acc[mt][nt][1]),
                      "+f"(acc[mt][nt][2]), "+f"(acc[mt][nt][3])
                    : "r"(__float_as_uint(alo.x)), "r"(__float_as_uint(ahi.x)),
                      "r"(__float_as_uint(alo.y)), "r"(__float_as_uint(ahi.y)),
                      "r"(__float_as_uint(bb[nt].x)), "r"(__float_as_uint(bb[nt].y)));
            // step B: thread k = {4tg+2, 4tg+3}
            #pragma unroll
            for (int nt = 0; nt < 4; nt++)
                asm volatile(
                    "mma.sync.aligned.m16n8k8.row.col.f32.tf32.tf32.f32 "
                    "{%0,%1,%2,%3}, {%4,%5,%6,%7}, {%8,%9}, {%0,%1,%2,%3};"
                    : "+f"(acc[mt][nt][0]), "+f"(acc[mt][nt][1]),
                      "+f"(acc[mt][nt][2]), "+f"(acc[mt][nt][3])
                    : "r"(__float_as_uint(alo.z)), "r"(__float_as_uint(ahi.z)),
                      "r"(__float_as_uint(alo.w)), "r"(__float_as_uint(ahi.w)),
                      "r"(__float_as_uint(bb[nt].z)), "r"(__float_as_uint(bb[nt].w)));
        }
        __syncthreads();
    }

    // Epilogue
    #pragma unroll
    for (int mt = 0; mt < 4; mt++) {
        int row0 = blockIdx.y * BM + wm * 64 + mt * 16 + g;
        #pragma unroll
        for (int nt = 0; nt < 4; nt++) {
            int col0 = blockIdx.x * BN + wn * 32 + nt * 8 + 2 * tg;
            float v0 = acc[mt][nt][0] * alpha;
            float v1 = acc[mt][nt][1] * alpha;
            float v2 = acc[mt][nt][2] * alpha;
            float v3 = acc[mt][nt][3] * alpha;
            if (ROUND) { v0 = f2tf(v0); v1 = f2tf(v1); v2 = f2tf(v2); v3 = f2tf(v3); }
            if (!TRANS) {
                *(float2*)&Cb[(long long)(row0    ) * ldc + col0] = make_float2(v0, v1);
                *(float2*)&Cb[(long long)(row0 + 8) * ldc + col0] = make_float2(v2, v3);
            } else {
                Cb[(long long)(col0    ) * ldc + row0    ] = v0;
                Cb[(long long)(col0 + 1) * ldc + row0    ] = v1;
                Cb[(long long)(col0    ) * ldc + row0 + 8] = v2;
                Cb[(long long)(col0 + 1) * ldc + row0 + 8] = v3;
            }
        }
    }
}

// Row softmax over SEQ-length rows, one block per row, in place; tf32-rounds output.
__global__ void softmax_kernel(float* __restrict__ S) {
    long long row = blockIdx.x;
    float4* p4 = (float4*)(S + row * SEQ);
    const int tid = threadIdx.x, lane = tid & 31, warp = tid >> 5;
    __shared__ float rmax[8], rsum[8];

    float4 v[4];
    float mx = -1e30f;
    #pragma unroll
    for (int i = 0; i < 4; i++) {
        v[i] = p4[tid + i * 256];
        mx = fmaxf(mx, fmaxf(fmaxf(v[i].x, v[i].y), fmaxf(v[i].z, v[i].w)));
    }
    #pragma unroll
    for (int o = 16; o > 0; o >>= 1) mx = fmaxf(mx, __shfl_xor_sync(0xffffffffu, mx, o));
    if (lane == 0) rmax[warp] = mx;
    __syncthreads();
    float gm = rmax[0];
    #pragma unroll
    for (int j = 1; j < 8; j++) gm = fmaxf(gm, rmax[j]);

    float s = 0.f;
    #pragma unroll
    for (int i = 0; i < 4; i++) {
        v[i].x = __expf(v[i].x - gm);
        v[i].y = __expf(v[i].y - gm);
        v[i].z = __expf(v[i].z - gm);
        v[i].w = __expf(v[i].w - gm);
        s += v[i].x + v[i].y + v[i].z + v[i].w;
    }
    #pragma unroll
    for (int o = 16; o > 0; o >>= 1) s += __shfl_xor_sync(0xffffffffu, s, o);
    if (lane == 0) rsum[warp] = s;
    __syncthreads();
    float gs = 0.f;
    #pragma unroll
    for (int j = 0; j < 8; j++) gs += rsum[j];
    float inv = 1.f / gs;

    #pragma unroll
    for (int i = 0; i < 4; i++) {
        v[i].x = f2tf(v[i].x * inv);
        v[i].y = f2tf(v[i].y * inv);
        v[i].z = f2tf(v[i].z * inv);
        v[i].w = f2tf(v[i].w * inv);
        p4[tid + i * 256] = v[i];
    }
}

extern "C" void kernel_launch(void* const* d_in, const int* in_sizes, int n_in,
                              void* d_out, int out_size) {
    const float* x  = (const float*)d_in[0];
    const float* Wq = (const float*)d_in[1];
    const float* Wk = (const float*)d_in[2];
    const float* Wv = (const float*)d_in[3];
    float* out = (float*)d_out;

    float *pX, *pWq, *pWk, *pWv, *pQ, *pK, *pVt, *pS;
    cudaGetSymbolAddress((void**)&pX,  g_X);
    cudaGetSymbolAddress((void**)&pWq, g_Wq);
    cudaGetSymbolAddress((void**)&pWk, g_Wk);
    cudaGetSymbolAddress((void**)&pWv, g_Wv);
    cudaGetSymbolAddress((void**)&pQ,  g_Q);
    cudaGetSymbolAddress((void**)&pK,  g_K);
    cudaGetSymbolAddress((void**)&pVt, g_Vt);
    cudaGetSymbolAddress((void**)&pS,  g_S);

    const long long BT = (long long)BATCH * SEQ;            // 16384
    const long long nX = BT * DIM;                          // 16M
    const long long nW = (long long)DIM * DIM;              // 1M
    const long long strideQK = (long long)SEQ * DIM;
    const long long strideS  = (long long)SEQ * SEQ;

    // Pre-round all GEMM inputs to tf32 (no in-loop cvt anywhere)
    round_tf32_kernel<<<(unsigned)(nX / 4 / 256), 256>>>(x,  pX,  nX);
    round_tf32_kernel<<<(unsigned)(nW / 4 / 256), 256>>>(Wq, pWq, nW);
    round_tf32_kernel<<<(unsigned)(nW / 4 / 256), 256>>>(Wk, pWk, nW);
    round_tf32_kernel<<<(unsigned)(nW / 4 / 256), 256>>>(Wv, pWv, nW);

    // Projections over flattened [B*T, D]; outputs tf32-rounded in epilogue
    dim3 gProj(DIM / BN, (unsigned)(BT / BM), 1);
    gemm_tf32<false, true><<<gProj, 256>>>(pX, pWq, pQ,  DIM, DIM, DIM,     0, 0, 0, DIM, 1.0f);
    gemm_tf32<false, true><<<gProj, 256>>>(pX, pWk, pK,  DIM, DIM, DIM,     0, 0, 0, DIM, 1.0f);
    gemm_tf32<true , true><<<gProj, 256>>>(pX, pWv, pVt, DIM, DIM, (int)BT, 0, 0, 0, DIM, 1.0f);

    // Scores: S_b = (Q_b K_b^T) / sqrt(D)   (softmax rounds its own output)
    dim3 gS(SEQ / BN, SEQ / BM, BATCH);
    gemm_tf32<false, false><<<gS, 256>>>(pQ, pK, pS, DIM, DIM, SEQ,
                                         strideQK, strideQK, strideS, DIM, 0.03125f);

    // Row softmax, in place (tf32-rounds probs)
    softmax_kernel<<<(unsigned)BT, 256>>>(pS);

    // Output: O_b = P_b V_b   (V^T layout: element (e, t) at e*BT + b*SEQ + t)
    dim3 gO(DIM / BN, SEQ / BM, BATCH);
    gemm_tf32<false, false><<<gO, 256>>>(pS, pVt, out, SEQ, (int)BT, DIM,
                                         strideS, (long long)SEQ, (long long)SEQ * DIM,
                                         SEQ, 1.0f);
}

// round 5
// speedup vs baseline: 2.3405x; 1.9271x over previous
#include <cuda_runtime.h>
#include <cuda_fp16.h>
#include <cstdint>

// Problem constants
#define BATCH 4
#define SEQ   4096
#define DIM   1024

// GEMM tile config (fp16 operands, f32 accum)
#define BM 128
#define BN 128
#define BK 32
#define NST 3
#define ASTAGE (BM * BK)   // halves per A stage (4096 halves = 8KB)
#define BSTAGE (BN * BK)

// Scratch (allocation-free rule: __device__ globals)
__device__ __half g_X [(long long)BATCH*SEQ*DIM];
__device__ __half g_Wq[(long long)DIM*DIM];
__device__ __half g_Wk[(long long)DIM*DIM];
__device__ __half g_Wv[(long long)DIM*DIM];
__device__ __half g_Q [(long long)BATCH*SEQ*DIM];
__device__ __half g_K [(long long)BATCH*SEQ*DIM];
__device__ __half g_Vt[(long long)BATCH*SEQ*DIM];  // [e][b*SEQ + t], ld = BATCH*SEQ
__device__ float  g_S [(long long)BATCH*SEQ*SEQ];  // scores f32, 256 MB
__device__ __half g_P [(long long)BATCH*SEQ*SEQ];  // probs fp16, 128 MB

__device__ __forceinline__ void cp16s(void* sm, const void* gm) {
    unsigned s = (unsigned)__cvta_generic_to_shared(sm);
    asm volatile("cp.async.cg.shared.global [%0], [%1], 16;" :: "r"(s), "l"(gm));
}

// f32 -> f16 conversion, 4 elems/thread
__global__ void to_half_kernel(const float* __restrict__ in, __half* __restrict__ out,
                               long long n) {
    long long i = ((long long)blockIdx.x * blockDim.x + threadIdx.x) * 4;
    if (i < n) {
        float4 v = *(const float4*)(in + i);
        __half2 h0 = __floats2half2_rn(v.x, v.y);
        __half2 h1 = __floats2half2_rn(v.z, v.w);
        *(uint2*)(out + i) = make_uint2(*(uint32_t*)&h0, *(uint32_t*)&h1);
    }
}

// C[M,N] = alpha * A[M,K] * B[N,K]^T, fp16 operands (K-contiguous), f32 accumulate.
//
// SMEM natural row layout, row stride BK halves (64B) — conflict-free LDS.128.
// k-permutation trick: one LDS.128 per row gives thread tg k = {8tg..8tg+7};
// mma step0 uses {8tg..8tg+3} (klo pair, khi pair), step1 uses {8tg+4..8tg+7}.
// A/B fragment slots agree thread-by-thread, quad covers all 32 k of the tile.
//
// OUT_HALF: write C as fp16 (else f32). TRANS: store C[n*ldc + m].
template<bool TRANS, bool OUT_HALF>
__global__ void __launch_bounds__(256, 2) gemm_f16(
    const __half* __restrict__ A, const __half* __restrict__ B, void* __restrict__ Cv,
    int lda, int ldb, int ldc,
    long long sA, long long sB, long long sC,
    int K, float alpha)
{
    __shared__ __half As[NST * ASTAGE];
    __shared__ __half Bs[NST * BSTAGE];

    const __half* Ab = A + (long long)blockIdx.z * sA + (long long)blockIdx.y * BM * lda;
    const __half* Bb = B + (long long)blockIdx.z * sB + (long long)blockIdx.x * BN * ldb;

    const int tid  = threadIdx.x;
    const int lane = tid & 31;
    const int warp = tid >> 5;
    const int wm = warp >> 2;      // 0..1
    const int wn = warp & 3;       // 0..3
    const int g  = lane >> 2;      // 0..7
    const int tg = lane & 3;       // 0..3

    // Loader: row = (tid>>2) + 64*i, 16B chunk = tid&3 (8 halves)
    const int lr = tid >> 2;
    const int lc8 = (tid & 3) * 8;
    const __half* Agl = Ab + (long long)lr * lda + lc8;
    const __half* Bgl = Bb + (long long)lr * ldb + lc8;

    float acc[4][4][4];
    #pragma unroll
    for (int i = 0; i < 4; i++)
        #pragma unroll
        for (int j = 0; j < 4; j++)
            #pragma unroll
            for (int c = 0; c < 4; c++) acc[i][j][c] = 0.f;

    const int KT = K / BK;

    auto load = [&](int kt, int st) {
        if (kt < KT) {
            __half* sa = As + st * ASTAGE;
            __half* sb = Bs + st * BSTAGE;
            #pragma unroll
            for (int i = 0; i < 2; i++)
                cp16s(&sa[(lr + i * 64) * BK + lc8],
                      Agl + kt * BK + (long long)(i * 64) * lda);
            #pragma unroll
            for (int i = 0; i < 2; i++)
                cp16s(&sb[(lr + i * 64) * BK + lc8],
                      Bgl + kt * BK + (long long)(i * 64) * ldb);
        }
        asm volatile("cp.async.commit_group;");
    };

    load(0, 0);
    load(1, 1);

    for (int kt = 0; kt < KT; kt++) {
        load(kt + 2, (kt + 2) % NST);
        asm volatile("cp.async.wait_group 2;");
        __syncthreads();

        const __half* as = As + (kt % NST) * ASTAGE;
        const __half* bs = Bs + (kt % NST) * BSTAGE;

        // B fragments: one LDS.128 per nt -> 8 halves (both k16 steps)
        uint4 bb[4];
        #pragma unroll
        for (int nt = 0; nt < 4; nt++) {
            int c0 = wn * 32 + nt * 8;
            bb[nt] = *(const uint4*)&bs[(c0 + g) * BK + tg * 8];
        }

        #pragma unroll
        for (int mt = 0; mt < 4; mt++) {
            int r0 = wm * 64 + mt * 16;
            uint4 alo = *(const uint4*)&as[(r0 + g    ) * BK + tg * 8];
            uint4 ahi = *(const uint4*)&as[(r0 + g + 8) * BK + tg * 8];
            // step 0: k = {8tg..8tg+3}; A regs {rowlo-klo, rowhi-klo, rowlo-khi, rowhi-khi}
            #pragma unroll
            for (int nt = 0; nt < 4; nt++)
                asm volatile(
                    "mma.sync.aligned.m16n8k16.row.col.f32.f16.f16.f32 "
                    "{%0,%1,%2,%3}, {%4,%5,%6,%7}, {%8,%9}, {%0,%1,%2,%3};"
                    : "+f"(acc[mt][nt][0]), "+f"(acc[mt][nt][1]),
                      "+f"(acc[mt][nt][2]), "+f"(acc[mt][nt][3])
                    : "r"(alo.x), "r"(ahi.x), "r"(alo.y), "r"(ahi.y),
                      "r"(bb[nt].x), "r"(bb[nt].y));
            // step 1: k = {8tg+4..8tg+7}
            #pragma unroll
            for (int nt = 0; nt < 4; nt++)
                asm volatile(
                    "mma.sync.aligned.m16n8k16.row.col.f32.f16.f16.f32 "
                    "{%0,%1,%2,%3}, {%4,%5,%6,%7}, {%8,%9}, {%0,%1,%2,%3};"
                    : "+f"(acc[mt][nt][0]), "+f"(acc[mt][nt][1]),
                      "+f"(acc[mt][nt][2]), "+f"(acc[mt][nt][3])
                    : "r"(alo.z), "r"(ahi.z), "r"(alo.w), "r"(ahi.w),
                      "r"(bb[nt].z), "r"(bb[nt].w));
        }
        __syncthreads();
    }

    // Epilogue
    #pragma unroll
    for (int mt = 0; mt < 4; mt++) {
        int row0 = blockIdx.y * BM + wm * 64 + mt * 16 + g;
        #pragma unroll
        for (int nt = 0; nt < 4; nt++) {
            int col0 = blockIdx.x * BN + wn * 32 + nt * 8 + 2 * tg;
            float v0 = acc[mt][nt][0] * alpha;
            float v1 = acc[mt][nt][1] * alpha;
            float v2 = acc[mt][nt][2] * alpha;
            float v3 = acc[mt][nt][3] * alpha;
            if (OUT_HALF) {
                __half* C = (__half*)Cv + (long long)blockIdx.z * sC;
                if (!TRANS) {
                    __half2 h01 = __floats2half2_rn(v0, v1);
                    __half2 h23 = __floats2half2_rn(v2, v3);
                    *(__half2*)&C[(long long)(row0    ) * ldc + col0] = h01;
                    *(__half2*)&C[(long long)(row0 + 8) * ldc + col0] = h23;
                } else {
                    C[(long long)(col0    ) * ldc + row0    ] = __float2half_rn(v0);
                    C[(long long)(col0 + 1) * ldc + row0    ] = __float2half_rn(v1);
                    C[(long long)(col0    ) * ldc + row0 + 8] = __float2half_rn(v2);
                    C[(long long)(col0 + 1) * ldc + row0 + 8] = __float2half_rn(v3);
                }
            } else {
                float* C = (float*)Cv + (long long)blockIdx.z * sC;
                if (!TRANS) {
                    *(float2*)&C[(long long)(row0    ) * ldc + col0] = make_float2(v0, v1);
                    *(float2*)&C[(long long)(row0 + 8) * ldc + col0] = make_float2(v2, v3);
                } else {
                    C[(long long)(col0    ) * ldc + row0    ] = v0;
                    C[(long long)(col0 + 1) * ldc + row0    ] = v1;
                    C[(long long)(col0    ) * ldc + row0 + 8] = v2;
                    C[(long long)(col0 + 1) * ldc + row0 + 8] = v3;
                }
            }
        }
    }
}

// Row softmax: read f32 scores row, write fp16 probs row.
__global__ void softmax_kernel(const float* __restrict__ S, __half* __restrict__ P) {
    long long row = blockIdx.x;
    const float4* p4 = (const float4*)(S + row * SEQ);
    uint2* o4 = (uint2*)(P + row * SEQ);
    const int tid = threadIdx.x, lane = tid & 31, warp = tid >> 5;
    __shared__ float rmax[8], rsum[8];

    float4 v[4];
    float mx = -1e30f;
    #pragma unroll
    for (int i = 0; i < 4; i++) {
        v[i] = p4[tid + i * 256];
        mx = fmaxf(mx, fmaxf(fmaxf(v[i].x, v[i].y), fmaxf(v[i].z, v[i].w)));
    }
    #pragma unroll
    for (int o = 16; o > 0; o >>= 1) mx = fmaxf(mx, __shfl_xor_sync(0xffffffffu, mx, o));
    if (lane == 0) rmax[warp] = mx;
    __syncthreads();
    float gm = rmax[0];
    #pragma unroll
    for (int j = 1; j < 8; j++) gm = fmaxf(gm, rmax[j]);

    float s = 0.f;
    #pragma unroll
    for (int i = 0; i < 4; i++) {
        v[i].x = __expf(v[i].x - gm);
        v[i].y = __expf(v[i].y - gm);
        v[i].z = __expf(v[i].z - gm);
        v[i].w = __expf(v[i].w - gm);
        s += v[i].x + v[i].y + v[i].z + v[i].w;
    }
    #pragma unroll
    for (int o = 16; o > 0; o >>= 1) s += __shfl_xor_sync(0xffffffffu, s, o);
    if (lane == 0) rsum[warp] = s;
    __syncthreads();
    float gs = 0.f;
    #pragma unroll
    for (int j = 0; j < 8; j++) gs += rsum[j];
    float inv = 1.f / gs;

    #pragma unroll
    for (int i = 0; i < 4; i++) {
        __half2 h0 = __floats2half2_rn(v[i].x * inv, v[i].y * inv);
        __half2 h1 = __floats2half2_rn(v[i].z * inv, v[i].w * inv);
        o4[tid + i * 256] = make_uint2(*(uint32_t*)&h0, *(uint32_t*)&h1);
    }
}

extern "C" void kernel_launch(void* const* d_in, const int* in_sizes, int n_in,
                              void* d_out, int out_size) {
    const float* x  = (const float*)d_in[0];
    const float* Wq = (const float*)d_in[1];
    const float* Wk = (const float*)d_in[2];
    const float* Wv = (const float*)d_in[3];
    float* out = (float*)d_out;

    __half *pX, *pWq, *pWk, *pWv, *pQ, *pK, *pVt, *pP;
    float *pS;
    cudaGetSymbolAddress((void**)&pX,  g_X);
    cudaGetSymbolAddress((void**)&pWq, g_Wq);
    cudaGetSymbolAddress((void**)&pWk, g_Wk);
    cudaGetSymbolAddress((void**)&pWv, g_Wv);
    cudaGetSymbolAddress((void**)&pQ,  g_Q);
    cudaGetSymbolAddress((void**)&pK,  g_K);
    cudaGetSymbolAddress((void**)&pVt, g_Vt);
    cudaGetSymbolAddress((void**)&pS,  g_S);
    cudaGetSymbolAddress((void**)&pP,  g_P);

    const long long BT = (long long)BATCH * SEQ;            // 16384
    const long long nX = BT * DIM;
    const long long nW = (long long)DIM * DIM;
    const long long strideQK = (long long)SEQ * DIM;
    const long long strideS  = (long long)SEQ * SEQ;

    // Convert inputs to fp16
    to_half_kernel<<<(unsigned)(nX / 4 / 256), 256>>>(x,  pX,  nX);
    to_half_kernel<<<(unsigned)(nW / 4 / 256), 256>>>(Wq, pWq, nW);
    to_half_kernel<<<(unsigned)(nW / 4 / 256), 256>>>(Wk, pWk, nW);
    to_half_kernel<<<(unsigned)(nW / 4 / 256), 256>>>(Wv, pWv, nW);

    // Projections: [B*T, D] x [D, D]^T -> fp16 outputs
    dim3 gProj(DIM / BN, (unsigned)(BT / BM), 1);
    gemm_f16<false, true ><<<gProj, 256>>>(pX, pWq, pQ,  DIM, DIM, DIM,     0, 0, 0, DIM, 1.0f);
    gemm_f16<false, true ><<<gProj, 256>>>(pX, pWk, pK,  DIM, DIM, DIM,     0, 0, 0, DIM, 1.0f);
    gemm_f16<true , true ><<<gProj, 256>>>(pX, pWv, pVt, DIM, DIM, (int)BT, 0, 0, 0, DIM, 1.0f);

    // Scores: S_b = (Q_b K_b^T) / sqrt(D) -> f32
    dim3 gS(SEQ / BN, SEQ / BM, BATCH);
    gemm_f16<false, false><<<gS, 256>>>(pQ, pK, pS, DIM, DIM, SEQ,
                                        strideQK, strideQK, strideS, DIM, 0.03125f);

    // Row softmax: f32 scores -> fp16 probs
    softmax_kernel<<<(unsigned)BT, 256>>>(pS, pP);

    // Output: O_b = P_b V_b -> f32 out  (Vt: [e][b*SEQ+t], ld BT, batch offset SEQ)
    dim3 gO(DIM / BN, SEQ / BM, BATCH);
    gemm_f16<false, false><<<gO, 256>>>(pP, pVt, out, SEQ, (int)BT, DIM,
                                        strideS, (long long)SEQ, (long long)SEQ * DIM,
                                        SEQ, 1.0f);
}

// round 6
// speedup vs baseline: 2.4768x; 1.0582x over previous
#include <cuda_runtime.h>
#include <cuda_fp16.h>
#include <cstdint>

// Problem constants
#define BATCH 4
#define SEQ   4096
#define DIM   1024

// GEMM tile config (fp16 operands, f32 accum)
// CTA tile 128x128, 4 warps, warp tile 64x64 (mt=4 x nt=8), BK=32, 3-stage cp.async.
#define BM 128
#define BN 128
#define BK 32
#define NST 3
#define ASTAGE (BM * BK)   // halves per A stage (4096 halves = 8KB)
#define BSTAGE (BN * BK)

// Scratch (allocation-free rule: __device__ globals)
__device__ __half g_X [(long long)BATCH*SEQ*DIM];
__device__ __half g_Wq[(long long)DIM*DIM];
__device__ __half g_Wk[(long long)DIM*DIM];
__device__ __half g_Wv[(long long)DIM*DIM];
__device__ __half g_Q [(long long)BATCH*SEQ*DIM];
__device__ __half g_K [(long long)BATCH*SEQ*DIM];
__device__ __half g_Vt[(long long)BATCH*SEQ*DIM];  // [e][b*SEQ + t], ld = BATCH*SEQ
__device__ float  g_S [(long long)BATCH*SEQ*SEQ];  // scores f32, 256 MB
__device__ __half g_P [(long long)BATCH*SEQ*SEQ];  // probs fp16, 128 MB

__device__ __forceinline__ void cp16s(void* sm, const void* gm) {
    unsigned s = (unsigned)__cvta_generic_to_shared(sm);
    asm volatile("cp.async.cg.shared.global [%0], [%1], 16;" :: "r"(s), "l"(gm));
}

// f32 -> f16 conversion, 4 elems/thread
__global__ void to_half_kernel(const float* __restrict__ in, __half* __restrict__ out,
                               long long n) {
    long long i = ((long long)blockIdx.x * blockDim.x + threadIdx.x) * 4;
    if (i < n) {
        float4 v = *(const float4*)(in + i);
        __half2 h0 = __floats2half2_rn(v.x, v.y);
        __half2 h1 = __floats2half2_rn(v.z, v.w);
        *(uint2*)(out + i) = make_uint2(*(uint32_t*)&h0, *(uint32_t*)&h1);
    }
}

// C[M,N] = alpha * A[M,K] * B[N,K]^T, fp16 operands (K-contiguous), f32 accumulate.
// k-permutation trick: one LDS.128 per row gives thread tg k = {8tg..8tg+7};
// mma step0 uses {8tg..8tg+3}, step1 uses {8tg+4..8tg+7}; A/B slots agree.
// OUT_HALF: write C as fp16 (else f32). TRANS: store C[n*ldc + m].
template<bool TRANS, bool OUT_HALF>
__global__ void __launch_bounds__(128, 2) gemm_f16(
    const __half* __restrict__ A, const __half* __restrict__ B, void* __restrict__ Cv,
    int lda, int ldb, int ldc,
    long long sA, long long sB, long long sC,
    int K, float alpha)
{
    __shared__ __half As[NST * ASTAGE];
    __shared__ __half Bs[NST * BSTAGE];

    const __half* Ab = A + (long long)blockIdx.z * sA + (long long)blockIdx.y * BM * lda;
    const __half* Bb = B + (long long)blockIdx.z * sB + (long long)blockIdx.x * BN * ldb;

    const int tid  = threadIdx.x;
    const int lane = tid & 31;
    const int warp = tid >> 5;      // 0..3
    const int wm = warp >> 1;       // 0..1
    const int wn = warp & 1;        // 0..1
    const int g  = lane >> 2;       // 0..7
    const int tg = lane & 3;        // 0..3

    // Loader: 128 threads, 4 cp16 per operand per stage.
    // row = (tid>>2) + 32*i, 16B chunk = (tid&3)*8 halves
    const int lr = tid >> 2;
    const int lc8 = (tid & 3) * 8;
    const __half* Agl = Ab + (long long)lr * lda + lc8;
    const __half* Bgl = Bb + (long long)lr * ldb + lc8;

    float acc[4][8][4];
    #pragma unroll
    for (int i = 0; i < 4; i++)
        #pragma unroll
        for (int j = 0; j < 8; j++)
            #pragma unroll
            for (int c = 0; c < 4; c++) acc[i][j][c] = 0.f;

    const int KT = K / BK;

    auto load = [&](int kt, int st) {
        if (kt < KT) {
            __half* sa = As + st * ASTAGE;
            __half* sb = Bs + st * BSTAGE;
            #pragma unroll
            for (int i = 0; i < 4; i++)
                cp16s(&sa[(lr + i * 32) * BK + lc8],
                      Agl + kt * BK + (long long)(i * 32) * lda);
            #pragma unroll
            for (int i = 0; i < 4; i++)
                cp16s(&sb[(lr + i * 32) * BK + lc8],
                      Bgl + kt * BK + (long long)(i * 32) * ldb);
        }
        asm volatile("cp.async.commit_group;");
    };

    load(0, 0);
    load(1, 1);

    for (int kt = 0; kt < KT; kt++) {
        asm volatile("cp.async.wait_group 1;");
        __syncthreads();
        // Overwrites stage (kt+2)%3 == (kt-1)%3: safe, all warps consumed it
        // before the barrier (mma.sync reads LDS operands synchronously).
        load(kt + 2, (kt + 2) % NST);

        const __half* as = As + (kt % NST) * ASTAGE;
        const __half* bs = Bs + (kt % NST) * BSTAGE;

        // B fragments: one LDS.128 per nt -> 8 halves (both k16 steps)
        uint4 bb[8];
        #pragma unroll
        for (int nt = 0; nt < 8; nt++) {
            int c0 = wn * 64 + nt * 8;
            bb[nt] = *(const uint4*)&bs[(c0 + g) * BK + tg * 8];
        }

        #pragma unroll
        for (int mt = 0; mt < 4; mt++) {
            int r0 = wm * 64 + mt * 16;
            uint4 alo = *(const uint4*)&as[(r0 + g    ) * BK + tg * 8];
            uint4 ahi = *(const uint4*)&as[(r0 + g + 8) * BK + tg * 8];
            // step 0: k = {8tg..8tg+3}
            #pragma unroll
            for (int nt = 0; nt < 8; nt++)
                asm volatile(
                    "mma.sync.aligned.m16n8k16.row.col.f32.f16.f16.f32 "
                    "{%0,%1,%2,%3}, {%4,%5,%6,%7}, {%8,%9}, {%0,%1,%2,%3};"
                    : "+f"(acc[mt][nt][0]), "+f"(acc[mt][nt][1]),
                      "+f"(acc[mt][nt][2]), "+f"(acc[mt][nt][3])
                    : "r"(alo.x), "r"(ahi.x), "r"(alo.y), "r"(ahi.y),
                      "r"(bb[nt].x), "r"(bb[nt].y));
            // step 1: k = {8tg+4..8tg+7}
            #pragma unroll
            for (int nt = 0; nt < 8; nt++)
                asm volatile(
                    "mma.sync.aligned.m16n8k16.row.col.f32.f16.f16.f32 "
                    "{%0,%1,%2,%3}, {%4,%5,%6,%7}, {%8,%9}, {%0,%1,%2,%3};"
                    : "+f"(acc[mt][nt][0]), "+f"(acc[mt][nt][1]),
                      "+f"(acc[mt][nt][2]), "+f"(acc[mt][nt][3])
                    : "r"(alo.z), "r"(ahi.z), "r"(alo.w), "r"(ahi.w),
                      "r"(bb[nt].z), "r"(bb[nt].w));
        }
    }

    // Epilogue
    #pragma unroll
    for (int mt = 0; mt < 4; mt++) {
        int row0 = blockIdx.y * BM + wm * 64 + mt * 16 + g;
        #pragma unroll
        for (int nt = 0; nt < 8; nt++) {
            int col0 = blockIdx.x * BN + wn * 64 + nt * 8 + 2 * tg;
            float v0 = acc[mt][nt][0] * alpha;
            float v1 = acc[mt][nt][1] * alpha;
            float v2 = acc[mt][nt][2] * alpha;
            float v3 = acc[mt][nt][3] * alpha;
            if (OUT_HALF) {
                __half* C = (__half*)Cv + (long long)blockIdx.z * sC;
                if (!TRANS) {
                    __half2 h01 = __floats2half2_rn(v0, v1);
                    __half2 h23 = __floats2half2_rn(v2, v3);
                    *(__half2*)&C[(long long)(row0    ) * ldc + col0] = h01;
                    *(__half2*)&C[(long long)(row0 + 8) * ldc + col0] = h23;
                } else {
                    C[(long long)(col0    ) * ldc + row0    ] = __float2half_rn(v0);
                    C[(long long)(col0 + 1) * ldc + row0    ] = __float2half_rn(v1);
                    C[(long long)(col0    ) * ldc + row0 + 8] = __float2half_rn(v2);
                    C[(long long)(col0 + 1) * ldc + row0 + 8] = __float2half_rn(v3);
                }
            } else {
                float* C = (float*)Cv + (long long)blockIdx.z * sC;
                if (!TRANS) {
                    *(float2*)&C[(long long)(row0    ) * ldc + col0] = make_float2(v0, v1);
                    *(float2*)&C[(long long)(row0 + 8) * ldc + col0] = make_float2(v2, v3);
                } else {
                    C[(long long)(col0    ) * ldc + row0    ] = v0;
                    C[(long long)(col0 + 1) * ldc + row0    ] = v1;
                    C[(long long)(col0    ) * ldc + row0 + 8] = v2;
                    C[(long long)(col0 + 1) * ldc + row0 + 8] = v3;
                }
            }
        }
    }
}

// Row softmax: read f32 scores row, write fp16 probs row.
__global__ void softmax_kernel(const float* __restrict__ S, __half* __restrict__ P) {
    long long row = blockIdx.x;
    const float4* p4 = (const float4*)(S + row * SEQ);
    uint2* o4 = (uint2*)(P + row * SEQ);
    const int tid = threadIdx.x, lane = tid & 31, warp = tid >> 5;
    __shared__ float rmax[8], rsum[8];

    float4 v[4];
    float mx = -1e30f;
    #pragma unroll
    for (int i = 0; i < 4; i++) {
        v[i] = p4[tid + i * 256];
        mx = fmaxf(mx, fmaxf(fmaxf(v[i].x, v[i].y), fmaxf(v[i].z, v[i].w)));
    }
    #pragma unroll
    for (int o = 16; o > 0; o >>= 1) mx = fmaxf(mx, __shfl_xor_sync(0xffffffffu, mx, o));
    if (lane == 0) rmax[warp] = mx;
    __syncthreads();
    float gm = rmax[0];
    #pragma unroll
    for (int j = 1; j < 8; j++) gm = fmaxf(gm, rmax[j]);

    float s = 0.f;
    #pragma unroll
    for (int i = 0; i < 4; i++) {
        v[i].x = __expf(v[i].x - gm);
        v[i].y = __expf(v[i].y - gm);
        v[i].z = __expf(v[i].z - gm);
        v[i].w = __expf(v[i].w - gm);
        s += v[i].x + v[i].y + v[i].z + v[i].w;
    }
    #pragma unroll
    for (int o = 16; o > 0; o >>= 1) s += __shfl_xor_sync(0xffffffffu, s, o);
    if (lane == 0) rsum[warp] = s;
    __syncthreads();
    float gs = 0.f;
    #pragma unroll
    for (int j = 0; j < 8; j++) gs += rsum[j];
    float inv = 1.f / gs;

    #pragma unroll
    for (int i = 0; i < 4; i++) {
        __half2 h0 = __floats2half2_rn(v[i].x * inv, v[i].y * inv);
        __half2 h1 = __floats2half2_rn(v[i].z * inv, v[i].w * inv);
        o4[tid + i * 256] = make_uint2(*(uint32_t*)&h0, *(uint32_t*)&h1);
    }
}

extern "C" void kernel_launch(void* const* d_in, const int* in_sizes, int n_in,
                              void* d_out, int out_size) {
    const float* x  = (const float*)d_in[0];
    const float* Wq = (const float*)d_in[1];
    const float* Wk = (const float*)d_in[2];
    const float* Wv = (const float*)d_in[3];
    float* out = (float*)d_out;

    __half *pX, *pWq, *pWk, *pWv, *pQ, *pK, *pVt, *pP;
    float *pS;
    cudaGetSymbolAddress((void**)&pX,  g_X);
    cudaGetSymbolAddress((void**)&pWq, g_Wq);
    cudaGetSymbolAddress((void**)&pWk, g_Wk);
    cudaGetSymbolAddress((void**)&pWv, g_Wv);
    cudaGetSymbolAddress((void**)&pQ,  g_Q);
    cudaGetSymbolAddress((void**)&pK,  g_K);
    cudaGetSymbolAddress((void**)&pVt, g_Vt);
    cudaGetSymbolAddress((void**)&pS,  g_S);
    cudaGetSymbolAddress((void**)&pP,  g_P);

    const long long BT = (long long)BATCH * SEQ;            // 16384
    const long long nX = BT * DIM;
    const long long nW = (long long)DIM * DIM;
    const long long strideQK = (long long)SEQ * DIM;
    const long long strideS  = (long long)SEQ * SEQ;

    // Convert inputs to fp16
    to_half_kernel<<<(unsigned)(nX / 4 / 256), 256>>>(x,  pX,  nX);
    to_half_kernel<<<(unsigned)(nW / 4 / 256), 256>>>(Wq, pWq, nW);
    to_half_kernel<<<(unsigned)(nW / 4 / 256), 256>>>(Wk, pWk, nW);
    to_half_kernel<<<(unsigned)(nW / 4 / 256), 256>>>(Wv, pWv, nW);

    // Projections: [B*T, D] x [D, D]^T -> fp16 outputs
    dim3 gProj(DIM / BN, (unsigned)(BT / BM), 1);
    gemm_f16<false, true ><<<gProj, 128>>>(pX, pWq, pQ,  DIM, DIM, DIM,     0, 0, 0, DIM, 1.0f);
    gemm_f16<false, true ><<<gProj, 128>>>(pX, pWk, pK,  DIM, DIM, DIM,     0, 0, 0, DIM, 1.0f);
    gemm_f16<true , true ><<<gProj, 128>>>(pX, pWv, pVt, DIM, DIM, (int)BT, 0, 0, 0, DIM, 1.0f);

    // Scores: S_b = (Q_b K_b^T) / sqrt(D) -> f32
    dim3 gS(SEQ / BN, SEQ / BM, BATCH);
    gemm_f16<false, false><<<gS, 128>>>(pQ, pK, pS, DIM, DIM, SEQ,
                                        strideQK, strideQK, strideS, DIM, 0.03125f);

    // Row softmax: f32 scores -> fp16 probs
    softmax_kernel<<<(unsigned)BT, 256>>>(pS, pP);

    // Output: O_b = P_b V_b -> f32 out  (Vt: [e][b*SEQ+t], ld BT, batch offset SEQ)
    dim3 gO(DIM / BN, SEQ / BM, BATCH);
    gemm_f16<false, false><<<gO, 128>>>(pP, pVt, out, SEQ, (int)BT, DIM,
                                        strideS, (long long)SEQ, (long long)SEQ * DIM,
                                        SEQ, 1.0f);
}

// round 7
// speedup vs baseline: 2.5647x; 1.0355x over previous
#include <cuda_runtime.h>
#include <cuda_fp16.h>
#include <cstdint>

// Problem constants
#define BATCH 4
#define SEQ   4096
#define DIM   1024
#define BT    (BATCH * SEQ)      // 16384

// GEMM tile config (fp16 operands, f32 accum)
// CTA tile 128x128, 4 warps, warp tile 64x64 (mt=4 x nt=8), BK=32, 3-stage cp.async.
#define BM 128
#define BN 128
#define BK 32
#define NST 3
#define ASTAGE (BM * BK)
#define BSTAGE (BN * BK)

// Epilogue modes
#define EPI_F32        0   // f32 out
#define EPI_HALF       1   // fp16 out
#define EPI_HALF_TRANS 2   // fp16 out, transposed store
#define EPI_EXP        3   // exp -> fp16 out + deterministic partial row sums
#define EPI_NORM       4   // f32 out scaled by per-row inv sum

// Scratch (allocation-free rule: __device__ globals)
__device__ __half g_X [(long long)BT*DIM];
__device__ __half g_Wq[(long long)DIM*DIM];
__device__ __half g_Wk[(long long)DIM*DIM];
__device__ __half g_Wv[(long long)DIM*DIM];
__device__ __half g_Q [(long long)BT*DIM];
__device__ __half g_K [(long long)BT*DIM];
__device__ __half g_Vt[(long long)BT*DIM];         // [e][b*SEQ + t], ld = BT
__device__ __half g_P [(long long)BATCH*SEQ*SEQ];  // unnormalized exp probs, fp16
__device__ float  g_psum[64LL * BT];               // partial row sums [slot][row]
__device__ float  g_inv [BT];                      // 1 / row sum

__device__ __forceinline__ void cp16s(void* sm, const void* gm) {
    unsigned s = (unsigned)__cvta_generic_to_shared(sm);
    asm volatile("cp.async.cg.shared.global [%0], [%1], 16;" :: "r"(s), "l"(gm));
}

// f32 -> f16 conversion, 4 elems/thread
__global__ void to_half_kernel(const float* __restrict__ in, __half* __restrict__ out,
                               long long n) {
    long long i = ((long long)blockIdx.x * blockDim.x + threadIdx.x) * 4;
    if (i < n) {
        float4 v = *(const float4*)(in + i);
        __half2 h0 = __floats2half2_rn(v.x, v.y);
        __half2 h1 = __floats2half2_rn(v.z, v.w);
        *(uint2*)(out + i) = make_uint2(*(uint32_t*)&h0, *(uint32_t*)&h1);
    }
}

// Sum 64 partials per row, store reciprocal. grid = BT/256, block 256.
__global__ void rowinv_kernel(const float* __restrict__ psum, float* __restrict__ inv) {
    int row = blockIdx.x * 256 + threadIdx.x;
    float s = 0.f;
    #pragma unroll
    for (int j = 0; j < 64; j++) s += psum[(long long)j * BT + row];
    inv[row] = 1.f / s;
}

// C[M,N] = alpha * A[M,K] * B[N,K]^T, fp16 operands (K-contiguous), f32 accumulate.
// k-permutation trick: one LDS.128 per row gives thread tg k = {8tg..8tg+7};
// mma step0 uses {8tg..8tg+3}, step1 uses {8tg+4..8tg+7}; A/B slots agree.
template<int EPI>
__global__ void __launch_bounds__(128, 2) gemm_f16(
    const __half* __restrict__ A, const __half* __restrict__ B, void* __restrict__ Cv,
    float* __restrict__ aux,   // EPI_EXP: psum base; EPI_NORM: inv base
    int lda, int ldb, int ldc,
    long long sA, long long sB, long long sC,
    int K, float alpha)
{
    __shared__ __half As[NST * ASTAGE];
    __shared__ __half Bs[NST * BSTAGE];

    const __half* Ab = A + (long long)blockIdx.z * sA + (long long)blockIdx.y * BM * lda;
    const __half* Bb = B + (long long)blockIdx.z * sB + (long long)blockIdx.x * BN * ldb;

    const int tid  = threadIdx.x;
    const int lane = tid & 31;
    const int warp = tid >> 5;      // 0..3
    const int wm = warp >> 1;       // 0..1
    const int wn = warp & 1;        // 0..1
    const int g  = lane >> 2;       // 0..7
    const int tg = lane & 3;        // 0..3

    const int lr = tid >> 2;
    const int lc8 = (tid & 3) * 8;
    const __half* Agl = Ab + (long long)lr * lda + lc8;
    const __half* Bgl = Bb + (long long)lr * ldb + lc8;

    float acc[4][8][4];
    #pragma unroll
    for (int i = 0; i < 4; i++)
        #pragma unroll
        for (int j = 0; j < 8; j++)
            #pragma unroll
            for (int c = 0; c < 4; c++) acc[i][j][c] = 0.f;

    const int KT = K / BK;

    auto load = [&](int kt, int st) {
        if (kt < KT) {
            __half* sa = As + st * ASTAGE;
            __half* sb = Bs + st * BSTAGE;
            #pragma unroll
            for (int i = 0; i < 4; i++)
                cp16s(&sa[(lr + i * 32) * BK + lc8],
                      Agl + kt * BK + (long long)(i * 32) * lda);
            #pragma unroll
            for (int i = 0; i < 4; i++)
                cp16s(&sb[(lr + i * 32) * BK + lc8],
                      Bgl + kt * BK + (long long)(i * 32) * ldb);
        }
        asm volatile("cp.async.commit_group;");
    };

    load(0, 0);
    load(1, 1);

    for (int kt = 0; kt < KT; kt++) {
        asm volatile("cp.async.wait_group 1;");
        __syncthreads();
        // Overwrites stage (kt+2)%3 == (kt-1)%3: safe, all warps consumed it
        // before the barrier (mma.sync reads LDS operands synchronously).
        load(kt + 2, (kt + 2) % NST);

        const __half* as = As + (kt % NST) * ASTAGE;
        const __half* bs = Bs + (kt % NST) * BSTAGE;

        uint4 bb[8];
        #pragma unroll
        for (int nt = 0; nt < 8; nt++) {
            int c0 = wn * 64 + nt * 8;
            bb[nt] = *(const uint4*)&bs[(c0 + g) * BK + tg * 8];
        }

        #pragma unroll
        for (int mt = 0; mt < 4; mt++) {
            int r0 = wm * 64 + mt * 16;
            uint4 alo = *(const uint4*)&as[(r0 + g    ) * BK + tg * 8];
            uint4 ahi = *(const uint4*)&as[(r0 + g + 8) * BK + tg * 8];
            #pragma unroll
            for (int nt = 0; nt < 8; nt++)
                asm volatile(
                    "mma.sync.aligned.m16n8k16.row.col.f32.f16.f16.f32 "
                    "{%0,%1,%2,%3}, {%4,%5,%6,%7}, {%8,%9}, {%0,%1,%2,%3};"
                    : "+f"(acc[mt][nt][0]), "+f"(acc[mt][nt][1]),
                      "+f"(acc[mt][nt][2]), "+f"(acc[mt][nt][3])
                    : "r"(alo.x), "r"(ahi.x), "r"(alo.y), "r"(ahi.y),
                      "r"(bb[nt].x), "r"(bb[nt].y));
            #pragma unroll
            for (int nt = 0; nt < 8; nt++)
                asm volatile(
                    "mma.sync.aligned.m16n8k16.row.col.f32.f16.f16.f32 "
                    "{%0,%1,%2,%3}, {%4,%5,%6,%7}, {%8,%9}, {%0,%1,%2,%3};"
                    : "+f"(acc[mt][nt][0]), "+f"(acc[mt][nt][1]),
                      "+f"(acc[mt][nt][2]), "+f"(acc[mt][nt][3])
                    : "r"(alo.z), "r"(ahi.z), "r"(alo.w), "r"(ahi.w),
                      "r"(bb[nt].z), "r"(bb[nt].w));
        }
    }

    // ---------------- Epilogue ----------------
    #pragma unroll
    for (int mt = 0; mt < 4; mt++) {
        int row0 = blockIdx.y * BM + wm * 64 + mt * 16 + g;   // within batch matrix
        float plo = 0.f, phi = 0.f;                            // EPI_EXP row partials
        float inv0 = 1.f, inv1 = 1.f;
        if (EPI == EPI_NORM) {
            const float* invp = aux + (long long)blockIdx.z * SEQ;
            inv0 = __ldg(&invp[row0]);
            inv1 = __ldg(&invp[row0 + 8]);
        }
        #pragma unroll
        for (int nt = 0; nt < 8; nt++) {
            int col0 = blockIdx.x * BN + wn * 64 + nt * 8 + 2 * tg;
            float v0 = acc[mt][nt][0] * alpha;
            float v1 = acc[mt][nt][1] * alpha;
            float v2 = acc[mt][nt][2] * alpha;
            float v3 = acc[mt][nt][3] * alpha;

            if (EPI == EPI_EXP) {
                __half* C = (__half*)Cv + (long long)blockIdx.z * sC;
                float e0 = __expf(fminf(v0, 11.f));
                float e1 = __expf(fminf(v1, 11.f));
                float e2 = __expf(fminf(v2, 11.f));
                float e3 = __expf(fminf(v3, 11.f));
                plo += e0 + e1; phi += e2 + e3;
                __half2 h01 = __floats2half2_rn(e0, e1);
                __half2 h23 = __floats2half2_rn(e2, e3);
                *(__half2*)&C[(long long)(row0    ) * ldc + col0] = h01;
                *(__half2*)&C[(long long)(row0 + 8) * ldc + col0] = h23;
            } else if (EPI == EPI_HALF) {
                __half* C = (__half*)Cv + (long long)blockIdx.z * sC;
                __half2 h01 = __floats2half2_rn(v0, v1);
                __half2 h23 = __floats2half2_rn(v2, v3);
                *(__half2*)&C[(long long)(row0    ) * ldc + col0] = h01;
                *(__half2*)&C[(long long)(row0 + 8) * ldc + col0] = h23;
            } else if (EPI == EPI_HALF_TRANS) {
                __half* C = (__half*)Cv + (long long)blockIdx.z * sC;
                C[(long long)(col0    ) * ldc + row0    ] = __float2half_rn(v0);
                C[(long long)(col0 + 1) * ldc + row0    ] = __float2half_rn(v1);
                C[(long long)(col0    ) * ldc + row0 + 8] = __float2half_rn(v2);
                C[(long long)(col0 + 1) * ldc + row0 + 8] = __float2half_rn(v3);
            } else if (EPI == EPI_NORM) {
                float* C = (float*)Cv + (long long)blockIdx.z * sC;
                *(float2*)&C[(long long)(row0    ) * ldc + col0] =
                    make_float2(v0 * inv0, v1 * inv0);
                *(float2*)&C[(long long)(row0 + 8) * ldc + col0] =
                    make_float2(v2 * inv1, v3 * inv1);
            } else {
                float* C = (float*)Cv + (long long)blockIdx.z * sC;
                *(float2*)&C[(long long)(row0    ) * ldc + col0] = make_float2(v0, v1);
                *(float2*)&C[(long long)(row0 + 8) * ldc + col0] = make_float2(v2, v3);
            }
        }
        if (EPI == EPI_EXP) {
            // quad reduce across tg (lane bits 0,1), then leader stores partials.
            plo += __shfl_xor_sync(0xffffffffu, plo, 1);
            plo += __shfl_xor_sync(0xffffffffu, plo, 2);
            phi += __shfl_xor_sync(0xffffffffu, phi, 1);
            phi += __shfl_xor_sync(0xffffffffu, phi, 2);
            if (tg == 0) {
                long long slot = (long long)(blockIdx.x * 2 + wn) * BT
                               + (long long)blockIdx.z * SEQ;
                aux[slot + row0    ] = plo;
                aux[slot + row0 + 8] = phi;
            }
        }
    }
}

extern "C" void kernel_launch(void* const* d_in, const int* in_sizes, int n_in,
                              void* d_out, int out_size) {
    const float* x  = (const float*)d_in[0];
    const float* Wq = (const float*)d_in[1];
    const float* Wk = (const float*)d_in[2];
    const float* Wv = (const float*)d_in[3];
    float* out = (float*)d_out;

    __half *pX, *pWq, *pWk, *pWv, *pQ, *pK, *pVt, *pP;
    float *pPsum, *pInv;
    cudaGetSymbolAddress((void**)&pX,  g_X);
    cudaGetSymbolAddress((void**)&pWq, g_Wq);
    cudaGetSymbolAddress((void**)&pWk, g_Wk);
    cudaGetSymbolAddress((void**)&pWv, g_Wv);
    cudaGetSymbolAddress((void**)&pQ,  g_Q);
    cudaGetSymbolAddress((void**)&pK,  g_K);
    cudaGetSymbolAddress((void**)&pVt, g_Vt);
    cudaGetSymbolAddress((void**)&pP,  g_P);
    cudaGetSymbolAddress((void**)&pPsum, g_psum);
    cudaGetSymbolAddress((void**)&pInv,  g_inv);

    const long long nX = (long long)BT * DIM;
    const long long nW = (long long)DIM * DIM;
    const long long strideQK = (long long)SEQ * DIM;
    const long long strideS  = (long long)SEQ * SEQ;

    // Convert inputs to fp16
    to_half_kernel<<<(unsigned)(nX / 4 / 256), 256>>>(x,  pX,  nX);
    to_half_kernel<<<(unsigned)(nW / 4 / 256), 256>>>(Wq, pWq, nW);
    to_half_kernel<<<(unsigned)(nW / 4 / 256), 256>>>(Wk, pWk, nW);
    to_half_kernel<<<(unsigned)(nW / 4 / 256), 256>>>(Wv, pWv, nW);

    // Projections: [B*T, D] x [D, D]^T -> fp16
    dim3 gProj(DIM / BN, BT / BM, 1);
    gemm_f16<EPI_HALF      ><<<gProj, 128>>>(pX, pWq, pQ,  nullptr, DIM, DIM, DIM, 0, 0, 0, DIM, 1.0f);
    gemm_f16<EPI_HALF      ><<<gProj, 128>>>(pX, pWk, pK,  nullptr, DIM, DIM, DIM, 0, 0, 0, DIM, 1.0f);
    gemm_f16<EPI_HALF_TRANS><<<gProj, 128>>>(pX, pWv, pVt, nullptr, DIM, DIM, BT,  0, 0, 0, DIM, 1.0f);

    // Scores + exp fused: P_b = exp(Q_b K_b^T / 32), partial row sums to psum
    dim3 gS(SEQ / BN, SEQ / BM, BATCH);
    gemm_f16<EPI_EXP><<<gS, 128>>>(pQ, pK, pP, pPsum, DIM, DIM, SEQ,
                                   strideQK, strideQK, strideS, DIM, 0.03125f);

    // Row sums -> reciprocals
    rowinv_kernel<<<BT / 256, 256>>>(pPsum, pInv);

    // Output: O_b = (P_b V_b) * inv_rowsum -> f32
    dim3 gO(DIM / BN, SEQ / BM, BATCH);
    gemm_f16<EPI_NORM><<<gO, 128>>>(pP, pVt, out, pInv, SEQ, BT, DIM,
                                    strideS, (long long)SEQ, (long long)SEQ * DIM,
                                    SEQ, 1.0f);
}

// round 8
// speedup vs baseline: 2.6275x; 1.0245x over previous
#include <cuda_runtime.h>
#include <cuda_fp16.h>
#include <cstdint>

// Problem constants
#define BATCH 4
#define SEQ   4096
#define DIM   1024
#define BT    (BATCH * SEQ)      // 16384

// GEMM tile config (fp16 operands, f32 accum)
// CTA tile 128x128, 4 warps, warp tile 64x64 (mt=4 x nt=8), BK=32, 3-stage cp.async.
#define BM 128
#define BN 128
#define BK 32
#define NST 3
#define ASTAGE (BM * BK)
#define BSTAGE (BN * BK)

// Epilogue modes
#define EPI_EXP   3   // exp -> fp16 out + deterministic partial row sums
#define EPI_NORM  4   // f32 out scaled by per-row inv sum
#define EPI_QKV   5   // fused QKV projection: z selects W + destination (z==2 transposed)

// Scratch (allocation-free rule: __device__ globals)
__device__ __half g_X [(long long)BT*DIM];
__device__ __half g_Wq[(long long)DIM*DIM];
__device__ __half g_Wk[(long long)DIM*DIM];
__device__ __half g_Wv[(long long)DIM*DIM];
__device__ __half g_Q [(long long)BT*DIM];
__device__ __half g_K [(long long)BT*DIM];
__device__ __half g_Vt[(long long)BT*DIM];         // [e][b*SEQ + t], ld = BT
__device__ __half g_P [(long long)BATCH*SEQ*SEQ];  // unnormalized exp probs, fp16
__device__ float  g_psum[64LL * BT];               // partial row sums [slot][row]
__device__ float  g_inv [BT];                      // 1 / row sum

__device__ __forceinline__ void cp16s(void* sm, const void* gm) {
    unsigned s = (unsigned)__cvta_generic_to_shared(sm);
    asm volatile("cp.async.cg.shared.global [%0], [%1], 16;" :: "r"(s), "l"(gm));
}

// f32 -> f16 conversion, 4 elems/thread (x input)
__global__ void to_half_kernel(const float* __restrict__ in, __half* __restrict__ out,
                               long long n) {
    long long i = ((long long)blockIdx.x * blockDim.x + threadIdx.x) * 4;
    if (i < n) {
        float4 v = *(const float4*)(in + i);
        __half2 h0 = __floats2half2_rn(v.x, v.y);
        __half2 h1 = __floats2half2_rn(v.z, v.w);
        *(uint2*)(out + i) = make_uint2(*(uint32_t*)&h0, *(uint32_t*)&h1);
    }
}

// All three weight converts in one launch: 1024 blocks per weight (1M elems each).
__global__ void w_to_half_kernel(const float* __restrict__ Wq,
                                 const float* __restrict__ Wk,
                                 const float* __restrict__ Wv) {
    int seg = blockIdx.x >> 10;
    const float* in = (seg == 0) ? Wq : (seg == 1) ? Wk : Wv;
    __half* out = (seg == 0) ? g_Wq : (seg == 1) ? g_Wk : g_Wv;
    long long i = (((long long)(blockIdx.x & 1023)) * 256 + threadIdx.x) * 4;
    float4 v = *(const float4*)(in + i);
    __half2 h0 = __floats2half2_rn(v.x, v.y);
    __half2 h1 = __floats2half2_rn(v.z, v.w);
    *(uint2*)(out + i) = make_uint2(*(uint32_t*)&h0, *(uint32_t*)&h1);
}

// Sum 64 partials per row, store reciprocal. grid = BT/256, block 256.
__global__ void rowinv_kernel(const float* __restrict__ psum, float* __restrict__ inv) {
    int row = blockIdx.x * 256 + threadIdx.x;
    float s = 0.f;
    #pragma unroll
    for (int j = 0; j < 64; j++) s += psum[(long long)j * BT + row];
    inv[row] = 1.f / s;
}

// C[M,N] = alpha * A[M,K] * B[N,K]^T, fp16 operands (K-contiguous), f32 accumulate.
// k-permutation trick: one LDS.128 per row gives thread tg k = {8tg..8tg+7};
// mma step0 uses {8tg..8tg+3}, step1 uses {8tg+4..8tg+7}; A/B slots agree.
// EPI_QKV: B/dest selected by blockIdx.z from the __device__ globals.
template<int EPI>
__global__ void __launch_bounds__(128, 2) gemm_f16(
    const __half* __restrict__ A, const __half* __restrict__ B, void* __restrict__ Cv,
    float* __restrict__ aux,   // EPI_EXP: psum base; EPI_NORM: inv base
    int lda, int ldb, int ldc,
    long long sA, long long sB, long long sC,
    int K, float alpha)
{
    __shared__ __half As[NST * ASTAGE];
    __shared__ __half Bs[NST * BSTAGE];

    const __half* Bsel = B;
    if (EPI == EPI_QKV)
        Bsel = (blockIdx.z == 0) ? g_Wq : (blockIdx.z == 1) ? g_Wk : g_Wv;

    const __half* Ab = A + (long long)blockIdx.z * sA + (long long)blockIdx.y * BM * lda;
    const __half* Bb = Bsel + ((EPI == EPI_QKV) ? 0 : (long long)blockIdx.z * sB)
                            + (long long)blockIdx.x * BN * ldb;

    const int tid  = threadIdx.x;
    const int lane = tid & 31;
    const int warp = tid >> 5;      // 0..3
    const int wm = warp >> 1;       // 0..1
    const int wn = warp & 1;        // 0..1
    const int g  = lane >> 2;       // 0..7
    const int tg = lane & 3;        // 0..3

    const int lr = tid >> 2;
    const int lc8 = (tid & 3) * 8;
    const __half* Agl = Ab + (long long)lr * lda + lc8;
    const __half* Bgl = Bb + (long long)lr * ldb + lc8;

    float acc[4][8][4];
    #pragma unroll
    for (int i = 0; i < 4; i++)
        #pragma unroll
        for (int j = 0; j < 8; j++)
            #pragma unroll
            for (int c = 0; c < 4; c++) acc[i][j][c] = 0.f;

    const int KT = K / BK;

    auto load = [&](int kt, int st) {
        if (kt < KT) {
            __half* sa = As + st * ASTAGE;
            __half* sb = Bs + st * BSTAGE;
            #pragma unroll
            for (int i = 0; i < 4; i++)
                cp16s(&sa[(lr + i * 32) * BK + lc8],
                      Agl + kt * BK + (long long)(i * 32) * lda);
            #pragma unroll
            for (int i = 0; i < 4; i++)
                cp16s(&sb[(lr + i * 32) * BK + lc8],
                      Bgl + kt * BK + (long long)(i * 32) * ldb);
        }
        asm volatile("cp.async.commit_group;");
    };

    load(0, 0);
    load(1, 1);

    for (int kt = 0; kt < KT; kt++) {
        asm volatile("cp.async.wait_group 1;");
        __syncthreads();
        // Overwrites stage (kt+2)%3 == (kt-1)%3: safe, all warps consumed it
        // before the barrier (mma.sync reads LDS operands synchronously).
        load(kt + 2, (kt + 2) % NST);

        const __half* as = As + (kt % NST) * ASTAGE;
        const __half* bs = Bs + (kt % NST) * BSTAGE;

        uint4 bb[8];
        #pragma unroll
        for (int nt = 0; nt < 8; nt++) {
            int c0 = wn * 64 + nt * 8;
            bb[nt] = *(const uint4*)&bs[(c0 + g) * BK + tg * 8];
        }

        #pragma unroll
        for (int mt = 0; mt < 4; mt++) {
            int r0 = wm * 64 + mt * 16;
            uint4 alo = *(const uint4*)&as[(r0 + g    ) * BK + tg * 8];
            uint4 ahi = *(const uint4*)&as[(r0 + g + 8) * BK + tg * 8];
            #pragma unroll
            for (int nt = 0; nt < 8; nt++)
                asm volatile(
                    "mma.sync.aligned.m16n8k16.row.col.f32.f16.f16.f32 "
                    "{%0,%1,%2,%3}, {%4,%5,%6,%7}, {%8,%9}, {%0,%1,%2,%3};"
                    : "+f"(acc[mt][nt][0]), "+f"(acc[mt][nt][1]),
                      "+f"(acc[mt][nt][2]), "+f"(acc[mt][nt][3])
                    : "r"(alo.x), "r"(ahi.x), "r"(alo.y), "r"(ahi.y),
                      "r"(bb[nt].x), "r"(bb[nt].y));
            #pragma unroll
            for (int nt = 0; nt < 8; nt++)
                asm volatile(
                    "mma.sync.aligned.m16n8k16.row.col.f32.f16.f16.f32 "
                    "{%0,%1,%2,%3}, {%4,%5,%6,%7}, {%8,%9}, {%0,%1,%2,%3};"
                    : "+f"(acc[mt][nt][0]), "+f"(acc[mt][nt][1]),
                      "+f"(acc[mt][nt][2]), "+f"(acc[mt][nt][3])
                    : "r"(alo.z), "r"(ahi.z), "r"(alo.w), "r"(ahi.w),
                      "r"(bb[nt].z), "r"(bb[nt].w));
        }
    }

    // ---------------- Epilogue ----------------
    const int zq = (EPI == EPI_QKV) ? (int)blockIdx.z : 0;
    __half* Cq = nullptr;
    int ldq = ldc;
    if (EPI == EPI_QKV) {
        Cq = (zq == 0) ? g_Q : (zq == 1) ? g_K : g_Vt;
        ldq = (zq == 2) ? BT : DIM;
    }

    #pragma unroll
    for (int mt = 0; mt < 4; mt++) {
        int row0 = blockIdx.y * BM + wm * 64 + mt * 16 + g;   // within batch matrix
        float plo = 0.f, phi = 0.f;                            // EPI_EXP row partials
        float inv0 = 1.f, inv1 = 1.f;
        if (EPI == EPI_NORM) {
            const float* invp = aux + (long long)blockIdx.z * SEQ;
            inv0 = __ldg(&invp[row0]);
            inv1 = __ldg(&invp[row0 + 8]);
        }
        #pragma unroll
        for (int nt = 0; nt < 8; nt++) {
            int col0 = blockIdx.x * BN + wn * 64 + nt * 8 + 2 * tg;
            float v0 = acc[mt][nt][0] * alpha;
            float v1 = acc[mt][nt][1] * alpha;
            float v2 = acc[mt][nt][2] * alpha;
            float v3 = acc[mt][nt][3] * alpha;

            if (EPI == EPI_QKV) {
                if (zq < 2) {
                    __half2 h01 = __floats2half2_rn(v0, v1);
                    __half2 h23 = __floats2half2_rn(v2, v3);
                    *(__half2*)&Cq[(long long)(row0    ) * ldq + col0] = h01;
                    *(__half2*)&Cq[(long long)(row0 + 8) * ldq + col0] = h23;
                } else {
                    Cq[(long long)(col0    ) * ldq + row0    ] = __float2half_rn(v0);
                    Cq[(long long)(col0 + 1) * ldq + row0    ] = __float2half_rn(v1);
                    Cq[(long long)(col0    ) * ldq + row0 + 8] = __float2half_rn(v2);
                    Cq[(long long)(col0 + 1) * ldq + row0 + 8] = __float2half_rn(v3);
                }
            } else if (EPI == EPI_EXP) {
                __half* C = (__half*)Cv + (long long)blockIdx.z * sC;
                float e0 = __expf(fminf(v0, 11.f));
                float e1 = __expf(fminf(v1, 11.f));
                float e2 = __expf(fminf(v2, 11.f));
                float e3 = __expf(fminf(v3, 11.f));
                plo += e0 + e1; phi += e2 + e3;
                __half2 h01 = __floats2half2_rn(e0, e1);
                __half2 h23 = __floats2half2_rn(e2, e3);
                *(__half2*)&C[(long long)(row0    ) * ldc + col0] = h01;
                *(__half2*)&C[(long long)(row0 + 8) * ldc + col0] = h23;
            } else { // EPI_NORM
                float* C = (float*)Cv + (long long)blockIdx.z * sC;
                *(float2*)&C[(long long)(row0    ) * ldc + col0] =
                    make_float2(v0 * inv0, v1 * inv0);
                *(float2*)&C[(long long)(row0 + 8) * ldc + col0] =
                    make_float2(v2 * inv1, v3 * inv1);
            }
        }
        if (EPI == EPI_EXP) {
            // quad reduce across tg (lane bits 0,1), then leader stores partials.
            plo += __shfl_xor_sync(0xffffffffu, plo, 1);
            plo += __shfl_xor_sync(0xffffffffu, plo, 2);
            phi += __shfl_xor_sync(0xffffffffu, phi, 1);
            phi += __shfl_xor_sync(0xffffffffu, phi, 2);
            if (tg == 0) {
                long long slot = (long long)(blockIdx.x * 2 + wn) * BT
                               + (long long)blockIdx.z * SEQ;
                aux[slot + row0    ] = plo;
                aux[slot + row0 + 8] = phi;
            }
        }
    }
}

extern "C" void kernel_launch(void* const* d_in, const int* in_sizes, int n_in,
                              void* d_out, int out_size) {
    const float* x  = (const float*)d_in[0];
    const float* Wq = (const float*)d_in[1];
    const float* Wk = (const float*)d_in[2];
    const float* Wv = (const float*)d_in[3];
    float* out = (float*)d_out;

    __half *pX, *pQ, *pK, *pVt, *pP;
    float *pPsum, *pInv;
    cudaGetSymbolAddress((void**)&pX,  g_X);
    cudaGetSymbolAddress((void**)&pQ,  g_Q);
    cudaGetSymbolAddress((void**)&pK,  g_K);
    cudaGetSymbolAddress((void**)&pVt, g_Vt);
    cudaGetSymbolAddress((void**)&pP,  g_P);
    cudaGetSymbolAddress((void**)&pPsum, g_psum);
    cudaGetSymbolAddress((void**)&pInv,  g_inv);

    const long long nX = (long long)BT * DIM;
    const long long strideQK = (long long)SEQ * DIM;
    const long long strideS  = (long long)SEQ * SEQ;

    // Convert inputs to fp16 (x + all three weights in 2 launches)
    to_half_kernel<<<(unsigned)(nX / 4 / 256), 256>>>(x, pX, nX);
    w_to_half_kernel<<<3 * 1024, 256>>>(Wq, Wk, Wv);

    // Fused QKV projections: one launch, z selects weight + destination.
    dim3 gProj(DIM / BN, BT / BM, 3);
    gemm_f16<EPI_QKV><<<gProj, 128>>>(pX, nullptr, nullptr, nullptr,
                                      DIM, DIM, DIM, 0, 0, 0, DIM, 1.0f);

    // Scores + exp fused: P_b = exp(Q_b K_b^T / 32), partial row sums to psum
    dim3 gS(SEQ / BN, SEQ / BM, BATCH);
    gemm_f16<EPI_EXP><<<gS, 128>>>(pQ, pK, pP, pPsum, DIM, DIM, SEQ,
                                   strideQK, strideQK, strideS, DIM, 0.03125f);

    // Row sums -> reciprocals
    rowinv_kernel<<<BT / 256, 256>>>(pPsum, pInv);

    // Output: O_b = (P_b V_b) * inv_rowsum -> f32
    dim3 gO(DIM / BN, SEQ / BM, BATCH);
    gemm_f16<EPI_NORM><<<gO, 128>>>(pP, pVt, out, pInv, SEQ, BT, DIM,
                                    strideS, (long long)SEQ, (long long)SEQ * DIM,
                                    SEQ, 1.0f);
}